// round 13
// baseline (speedup 1.0000x reference)
#include <cuda_runtime.h>
#include <cuda_fp16.h>
#include <cstdint>

#define P_PIX 32768            // H*W
#define HP    16384            // P/2
#define HPH   8192             // HP/2

// ---------------- scratch (static device globals) ----------------------------
__device__ __half g_H  [128u * 32768u];         //  8 MB hidden [128][P]
__device__ __half g_X  [256u * 32768u];         // 16 MB query_state fp16 [256][P]
__device__ __half g_Q  [256u * 32768u];         // 16 MB
__device__ __half g_KV [4u * 512u * 32768u];    // 128 MB per collab: K rows 0..255, V rows 256..511
__device__ __half g_A  [256u * 32768u];         // 16 MB
__device__ __half g_C16[4u * 256u * 32768u];    // 64 MB collaborator features fp16 [4][256][P]
__device__ __half g_Wd2[256 * 128];
__device__ __half g_Wq [256 * 256];
__device__ __half g_Wkv[512 * 256];             // [wk ; wv]
__device__ __half g_Wo [256 * 256];
__device__ float  g_bkv[512];

// ---------------- PTX helpers -------------------------------------------------
__device__ __forceinline__ void ldmx4(uint32_t& r0, uint32_t& r1, uint32_t& r2, uint32_t& r3, uint32_t addr) {
    asm volatile("ldmatrix.sync.aligned.m8n8.x4.shared.b16 {%0,%1,%2,%3}, [%4];\n"
                 : "=r"(r0), "=r"(r1), "=r"(r2), "=r"(r3) : "r"(addr));
}
__device__ __forceinline__ void ldmx4t(uint32_t& r0, uint32_t& r1, uint32_t& r2, uint32_t& r3, uint32_t addr) {
    asm volatile("ldmatrix.sync.aligned.m8n8.x4.trans.shared.b16 {%0,%1,%2,%3}, [%4];\n"
                 : "=r"(r0), "=r"(r1), "=r"(r2), "=r"(r3) : "r"(addr));
}
__device__ __forceinline__ void mma16816(float* d, const uint32_t* a, uint32_t b0, uint32_t b1) {
    asm volatile("mma.sync.aligned.m16n8k16.row.col.f32.f16.f16.f32 "
                 "{%0,%1,%2,%3}, {%4,%5,%6,%7}, {%8,%9}, {%0,%1,%2,%3};\n"
                 : "+f"(d[0]), "+f"(d[1]), "+f"(d[2]), "+f"(d[3])
                 : "r"(a[0]), "r"(a[1]), "r"(a[2]), "r"(a[3]), "r"(b0), "r"(b1));
}
__device__ __forceinline__ void cp16(uint32_t dst, const void* src) {
    asm volatile("cp.async.cg.shared.global [%0], [%1], 16;\n" :: "r"(dst), "l"(src));
}
__device__ __forceinline__ void cp_commit() { asm volatile("cp.async.commit_group;\n"); }
template<int N> __device__ __forceinline__ void cp_wait() {
    asm volatile("cp.async.wait_group %0;\n" :: "n"(N));
}

// ---------------- prep ---------------------------------------------------------
__global__ __launch_bounds__(256)
void prep_all(const float* __restrict__ wd2, const float* __restrict__ wq,
              const float* __restrict__ wk, const float* __restrict__ wv,
              const float* __restrict__ wo, const float* __restrict__ bk,
              const float* __restrict__ bv,
              __half* __restrict__ Wd2, __half* __restrict__ Wq,
              __half* __restrict__ Wkv, __half* __restrict__ Wo,
              float* __restrict__ bkv)
{
    int t = blockIdx.x * 256 + threadIdx.x;
    if (t < 32768)       Wd2[t] = __float2half_rn(wd2[t]);
    else if (t < 98304)  { int i = t - 32768;  Wq[i]  = __float2half_rn(wq[i]); }
    else if (t < 163840) { int i = t - 98304;  Wkv[i] = __float2half_rn(wk[i]); }
    else if (t < 229376) { int i = t - 163840; Wkv[65536 + i] = __float2half_rn(wv[i]); }
    else if (t < 294912) { int i = t - 229376; Wo[i]  = __float2half_rn(wo[i]); }
    else if (t < 295424) { int i = t - 294912; bkv[i] = (i < 256) ? bk[i] : bv[i - 256]; }
}

// ---------------- collaborator fp32 -> fp16 (8 elems/thread, one collab) -------
__global__ __launch_bounds__(256)
void conv_coll(const float* __restrict__ s, __half* __restrict__ d)
{
    int t = blockIdx.x * 256 + threadIdx.x;
    float4 a = reinterpret_cast<const float4*>(s)[2 * t];
    float4 b = reinterpret_cast<const float4*>(s)[2 * t + 1];
    __half2 h0 = __floats2half2_rn(a.x, a.y), h1 = __floats2half2_rn(a.z, a.w);
    __half2 h2 = __floats2half2_rn(b.x, b.y), h3 = __floats2half2_rn(b.z, b.w);
    reinterpret_cast<uint4*>(d)[t] = make_uint4(
        *reinterpret_cast<uint32_t*>(&h0), *reinterpret_cast<uint32_t*>(&h1),
        *reinterpret_cast<uint32_t*>(&h2), *reinterpret_cast<uint32_t*>(&h3));
}

// ---------------- demand hidden ------------------------------------------------
__global__ __launch_bounds__(256)
void hid_kernel(const float* __restrict__ D, const float* __restrict__ w1,
                const float* __restrict__ b1, __half* __restrict__ Hout)
{
    int t = blockIdx.x * blockDim.x + threadIdx.x;
    int p = t & (P_PIX - 1);
    int c = t >> 15;
    float h = b1[c]
            + w1[c * 3 + 0] * D[p]
            + w1[c * 3 + 1] * D[P_PIX + p]
            + w1[c * 3 + 2] * D[2 * P_PIX + p];
    Hout[(size_t)c * P_PIX + p] = __float2half_rn(fmaxf(h, 0.f));
}

// ---------------- pipelined fp16 tensor-core GEMM (64x64 warp tiles) ------------
constexpr int ASZ   = 128 * 40;
constexpr int BSZ16 = 32 * 136;
constexpr int NS16  = 4;
constexpr int SMEM16 = NS16 * (ASZ + BSZ16) * 2;   // 75776 B -> 2 CTAs/SM

template<bool ADD2, bool OUT_HALF>
__global__ __launch_bounds__(128)
void gemm_pipe(const __half* __restrict__ W, const float* __restrict__ bias,
               const __half* __restrict__ B,
               const float* __restrict__ add1, const float* __restrict__ add2,
               void* __restrict__ Cv,
               int K, int ldb, int ldc)
{
    constexpr int NS = NS16;
    extern __shared__ __half smem[];
    __half* Asm = smem;
    __half* Bsm = smem + NS * ASZ;

    const int tid  = threadIdx.x;
    const int lane = tid & 31;
    const int warp = tid >> 5;
    const int warp_row = (warp & 1) * 64;
    const int warp_col = (warp >> 1) * 64;

    const int mtile0 = blockIdx.x * 128;
    const int p0     = blockIdx.y * 128;

    const int KT = K >> 5;

    auto load_stage = [&](int kt, int s) {
        int k0 = kt << 5;
        __half* As = Asm + s * ASZ;
        __half* Bs = Bsm + s * BSZ16;
        #pragma unroll
        for (int i = 0; i < 4; i++) {
            int idx = tid + i * 128;
            int r = idx >> 2, c8 = (idx & 3) << 3;
            cp16((uint32_t)__cvta_generic_to_shared(As + r * 40 + c8),
                 W + (size_t)(mtile0 + r) * K + k0 + c8);
        }
        #pragma unroll
        for (int i = 0; i < 4; i++) {
            int idx = tid + i * 128;
            int r = idx >> 4, c8 = (idx & 15) << 3;
            cp16((uint32_t)__cvta_generic_to_shared(Bs + r * 136 + c8),
                 B + (size_t)(k0 + r) * ldb + p0 + c8);
        }
    };

    float acc[4][8][4];
    #pragma unroll
    for (int i = 0; i < 4; i++)
        #pragma unroll
        for (int j = 0; j < 8; j++)
            #pragma unroll
            for (int t = 0; t < 4; t++) acc[i][j][t] = 0.f;

    #pragma unroll
    for (int s = 0; s < NS - 1; s++) {
        if (s < KT) load_stage(s, s);
        cp_commit();
    }

    for (int kt = 0; kt < KT; kt++) {
        cp_wait<NS - 2>();
        __syncthreads();

        int nk = kt + NS - 1;
        if (nk < KT) load_stage(nk, nk % NS);
        cp_commit();

        const int sc = kt % NS;
        const __half* As = Asm + sc * ASZ;
        const __half* Bs = Bsm + sc * BSZ16;

        #pragma unroll
        for (int kk = 0; kk < 32; kk += 16) {
            uint32_t a[4][4];
            #pragma unroll
            for (int mt = 0; mt < 4; mt++) {
                uint32_t addr = (uint32_t)__cvta_generic_to_shared(
                    As + (warp_row + mt * 16 + (lane & 15)) * 40 + kk + ((lane >> 4) << 3));
                ldmx4(a[mt][0], a[mt][1], a[mt][2], a[mt][3], addr);
            }
            #pragma unroll
            for (int j = 0; j < 4; j++) {
                uint32_t b0, b1, b2, b3;
                uint32_t addr = (uint32_t)__cvta_generic_to_shared(
                    Bs + (kk + (lane & 15)) * 136 + warp_col + j * 16 + ((lane >> 4) << 3));
                ldmx4t(b0, b1, b2, b3, addr);
                #pragma unroll
                for (int mt = 0; mt < 4; mt++) {
                    mma16816(acc[mt][2 * j],     a[mt], b0, b1);
                    mma16816(acc[mt][2 * j + 1], a[mt], b2, b3);
                }
            }
        }
    }

    // epilogue
    __half* Ch = (__half*)Cv;
    float*  Cf = (float*)Cv;
    #pragma unroll
    for (int mt = 0; mt < 4; mt++) {
        int r = warp_row + mt * 16 + (lane >> 2);
        #pragma unroll
        for (int rr = 0; rr < 2; rr++) {
            int gr = mtile0 + r + rr * 8;
            float bsv = bias[gr];
            #pragma unroll
            for (int j = 0; j < 8; j++) {
                int px = p0 + warp_col + j * 8 + ((lane & 3) << 1);
                float v0 = acc[mt][j][rr * 2 + 0] + bsv;
                float v1 = acc[mt][j][rr * 2 + 1] + bsv;
                if (ADD2) {
                    size_t off = (size_t)gr * ldc + px;
                    float2 a1 = *reinterpret_cast<const float2*>(add1 + off);
                    float2 a2 = *reinterpret_cast<const float2*>(add2 + off);
                    v0 += a1.x + a2.x;
                    v1 += a1.y + a2.y;
                }
                if (OUT_HALF) {
                    *reinterpret_cast<__half2*>(Ch + (size_t)gr * ldc + px) =
                        __floats2half2_rn(v0, v1);
                } else {
                    *reinterpret_cast<float2*>(Cf + (size_t)gr * ldc + px) =
                        make_float2(v0, v1);
                }
            }
        }
    }
}

// ---------------- per-pixel cross attention (half2, 2 px/thread, half-range) ---
__global__ __launch_bounds__(256)
void attn_kernel(const __half* __restrict__ Q, const __half* __restrict__ KV,
                 __half* __restrict__ A, int ppOff)
{
    int t = blockIdx.x * blockDim.x + threadIdx.x;
    int pp = ppOff + (t & (HPH - 1));
    int h  = t >> 13;

    const __half2* Q2 = reinterpret_cast<const __half2*>(Q + (size_t)h * 32 * P_PIX) + pp;
    float2 q[32];
    #pragma unroll
    for (int d = 0; d < 32; d++) q[d] = __half22float2(Q2[(size_t)d * HP]);

    float2 s[4];
    #pragma unroll
    for (int n = 0; n < 4; n++) {
        const __half2* K2 = reinterpret_cast<const __half2*>(
            KV + (size_t)n * 512 * P_PIX + (size_t)h * 32 * P_PIX) + pp;
        float ax = 0.f, ay = 0.f;
        #pragma unroll
        for (int d = 0; d < 32; d++) {
            float2 k = __half22float2(K2[(size_t)d * HP]);
            ax = fmaf(q[d].x, k.x, ax);
            ay = fmaf(q[d].y, k.y, ay);
        }
        s[n] = make_float2(ax * 0.17677669529663687f, ay * 0.17677669529663687f);
    }
    float mx = fmaxf(fmaxf(s[0].x, s[1].x), fmaxf(s[2].x, s[3].x));
    float my = fmaxf(fmaxf(s[0].y, s[1].y), fmaxf(s[2].y, s[3].y));
    float wx[4], wy[4], sx = 0.f, sy = 0.f;
    #pragma unroll
    for (int n = 0; n < 4; n++) {
        wx[n] = __expf(s[n].x - mx); sx += wx[n];
        wy[n] = __expf(s[n].y - my); sy += wy[n];
    }
    float ix = 1.f / sx, iy = 1.f / sy;
    #pragma unroll
    for (int n = 0; n < 4; n++) { wx[n] *= ix; wy[n] *= iy; }

    __half2* A2 = reinterpret_cast<__half2*>(A + (size_t)h * 32 * P_PIX) + pp;
    #pragma unroll
    for (int d = 0; d < 32; d++) {
        float ox = 0.f, oy = 0.f;
        #pragma unroll
        for (int n = 0; n < 4; n++) {
            float2 v = __half22float2(*(reinterpret_cast<const __half2*>(
                KV + (size_t)n * 512 * P_PIX + (size_t)(256 + h * 32 + d) * P_PIX) + pp));
            ox = fmaf(wx[n], v.x, ox);
            oy = fmaf(wy[n], v.y, oy);
        }
        A2[(size_t)d * HP] = __floats2half2_rn(ox, oy);
    }
}

// ---------------- launch ------------------------------------------------------
extern "C" void kernel_launch(void* const* d_in, const int* in_sizes, int n_in,
                              void* d_out, int out_size)
{
    const float* ego  = (const float*)d_in[0];
    const float* dem  = (const float*)d_in[1];
    const float* coll = (const float*)d_in[2];
    const float* w_d1 = (const float*)d_in[3];
    const float* b_d1 = (const float*)d_in[4];
    const float* w_d2 = (const float*)d_in[5];
    const float* b_d2 = (const float*)d_in[6];
    const float* wq   = (const float*)d_in[7];
    const float* bq   = (const float*)d_in[8];
    const float* wk   = (const float*)d_in[9];
    const float* bk   = (const float*)d_in[10];
    const float* wv   = (const float*)d_in[11];
    const float* bv   = (const float*)d_in[12];
    const float* wo   = (const float*)d_in[13];
    const float* bo   = (const float*)d_in[14];
    const float* pos  = (const float*)d_in[15];

    __half *H, *X, *Qb, *KV, *A, *C16, *Wd2, *Wq, *Wkv, *Wo;
    float *bkv;
    cudaGetSymbolAddress((void**)&H,   g_H);
    cudaGetSymbolAddress((void**)&X,   g_X);
    cudaGetSymbolAddress((void**)&Qb,  g_Q);
    cudaGetSymbolAddress((void**)&KV,  g_KV);
    cudaGetSymbolAddress((void**)&A,   g_A);
    cudaGetSymbolAddress((void**)&C16, g_C16);
    cudaGetSymbolAddress((void**)&Wd2, g_Wd2);
    cudaGetSymbolAddress((void**)&Wq,  g_Wq);
    cudaGetSymbolAddress((void**)&Wkv, g_Wkv);
    cudaGetSymbolAddress((void**)&Wo,  g_Wo);
    cudaGetSymbolAddress((void**)&bkv, g_bkv);

    static cudaStream_t s2 = nullptr, s3 = nullptr;
    static cudaEvent_t evP = nullptr, evKV = nullptr, evA1 = nullptr, evO1 = nullptr;
    static cudaEvent_t evC[4] = {nullptr, nullptr, nullptr, nullptr};
    if (!s2) {
        cudaStreamCreateWithFlags(&s2, cudaStreamNonBlocking);
        cudaStreamCreateWithFlags(&s3, cudaStreamNonBlocking);
        cudaEventCreateWithFlags(&evP,  cudaEventDisableTiming);
        cudaEventCreateWithFlags(&evKV, cudaEventDisableTiming);
        cudaEventCreateWithFlags(&evA1, cudaEventDisableTiming);
        cudaEventCreateWithFlags(&evO1, cudaEventDisableTiming);
        for (int n = 0; n < 4; n++)
            cudaEventCreateWithFlags(&evC[n], cudaEventDisableTiming);

        cudaFuncSetAttribute(gemm_pipe<true, true>,
                             cudaFuncAttributeMaxDynamicSharedMemorySize, SMEM16);
        cudaFuncSetAttribute(gemm_pipe<false, true>,
                             cudaFuncAttributeMaxDynamicSharedMemorySize, SMEM16);
        cudaFuncSetAttribute(gemm_pipe<false, false>,
                             cudaFuncAttributeMaxDynamicSharedMemorySize, SMEM16);
    }

    const int P = P_PIX;

    // ---- prep, then fork
    prep_all<<<1154, 256>>>(w_d2, wq, wk, wv, wo, bk, bv, Wd2, Wq, Wkv, Wo, bkv);
    cudaEventRecord(evP, 0);

    // ---- s2: per-collaborator fp32->fp16 conversion chunks (DRAM pipe)
    cudaStreamWaitEvent(s2, evP, 0);
    for (int n = 0; n < 4; n++) {
        conv_coll<<<4096, 256, 0, s2>>>(coll + (size_t)n * 256 * P,
                                        C16 + (size_t)n * 256 * P);
        cudaEventRecord(evC[n], s2);
    }

    // ---- s3: per-collaborator stacked [K;V] GEMM (M=512, grid 4x256), pipelined
    cudaStreamWaitEvent(s3, evP, 0);
    for (int n = 0; n < 4; n++) {
        cudaStreamWaitEvent(s3, evC[n], 0);
        gemm_pipe<false, true><<<dim3(4, P / 128), 128, SMEM16, s3>>>(
            Wkv, bkv, C16 + (size_t)n * 256 * P, nullptr, nullptr,
            (void*)(KV + (size_t)n * 512 * P), 256, P, P);
    }
    cudaEventRecord(evKV, s3);

    // ---- main stream: hid -> X -> Q (tensor; runs under KV's shadow)
    hid_kernel<<<(128 * P) / 256, 256>>>(dem, w_d1, b_d1, H);
    gemm_pipe<true, true><<<dim3(2, P / 128), 128, SMEM16>>>(
        Wd2, b_d2, H, ego, pos, X, 128, P, P);
    gemm_pipe<false, true><<<dim3(2, P / 128), 128, SMEM16>>>(
        Wq, bq, X, nullptr, nullptr, Qb, 256, P, P);

    // ---- join: attention half 1
    cudaStreamWaitEvent(0, evKV, 0);
    attn_kernel<<<(8 * HPH) / 256, 256>>>(Qb, KV, A, 0);
    cudaEventRecord(evA1, 0);

    // ---- O(half1) on s2 concurrently with attn(half2)
    cudaStreamWaitEvent(s2, evA1, 0);
    gemm_pipe<false, false><<<dim3(2, (P / 2) / 128), 128, SMEM16, s2>>>(
        Wo, bo, A, nullptr, nullptr, d_out, 256, P, P);
    cudaEventRecord(evO1, s2);

    attn_kernel<<<(8 * HPH) / 256, 256>>>(Qb, KV, A, HPH);

    // ---- O(half2)
    gemm_pipe<false, false><<<dim3(2, (P / 2) / 128), 128, SMEM16>>>(
        Wo, bo, A + HP, nullptr, nullptr, (float*)d_out + HP, 256, P, P);

    cudaStreamWaitEvent(0, evO1, 0);
}

// round 14
// speedup vs baseline: 1.0282x; 1.0282x over previous
#include <cuda_runtime.h>
#include <cuda_fp16.h>
#include <cstdint>

#define P_PIX 32768            // H*W
#define HP    16384            // P/2
#define HPH   8192             // HP/2

// ---------------- scratch (static device globals) ----------------------------
__device__ __half g_H  [128u * 32768u];         //  8 MB hidden [128][P]
__device__ __half g_X  [256u * 32768u];         // 16 MB query_state fp16 [256][P]
__device__ __half g_Q  [256u * 32768u];         // 16 MB
__device__ __half g_KV [4u * 512u * 32768u];    // 128 MB per collab: K rows 0..255, V rows 256..511
__device__ __half g_A  [256u * 32768u];         // 16 MB
__device__ __half g_C16[4u * 256u * 32768u];    // 64 MB collaborator features fp16 [4][256][P]
__device__ __half g_Wd2[256 * 128];
__device__ __half g_Wq [256 * 256];
__device__ __half g_Wkv[512 * 256];
__device__ __half g_Wo [256 * 256];
__device__ float  g_bkv[512];

// ---------------- PTX helpers -------------------------------------------------
__device__ __forceinline__ void ldmx4(uint32_t& r0, uint32_t& r1, uint32_t& r2, uint32_t& r3, uint32_t addr) {
    asm volatile("ldmatrix.sync.aligned.m8n8.x4.shared.b16 {%0,%1,%2,%3}, [%4];\n"
                 : "=r"(r0), "=r"(r1), "=r"(r2), "=r"(r3) : "r"(addr));
}
__device__ __forceinline__ void ldmx4t(uint32_t& r0, uint32_t& r1, uint32_t& r2, uint32_t& r3, uint32_t addr) {
    asm volatile("ldmatrix.sync.aligned.m8n8.x4.trans.shared.b16 {%0,%1,%2,%3}, [%4];\n"
                 : "=r"(r0), "=r"(r1), "=r"(r2), "=r"(r3) : "r"(addr));
}
__device__ __forceinline__ void mma16816(float* d, const uint32_t* a, uint32_t b0, uint32_t b1) {
    asm volatile("mma.sync.aligned.m16n8k16.row.col.f32.f16.f16.f32 "
                 "{%0,%1,%2,%3}, {%4,%5,%6,%7}, {%8,%9}, {%0,%1,%2,%3};\n"
                 : "+f"(d[0]), "+f"(d[1]), "+f"(d[2]), "+f"(d[3])
                 : "r"(a[0]), "r"(a[1]), "r"(a[2]), "r"(a[3]), "r"(b0), "r"(b1));
}
__device__ __forceinline__ void mma16816h(uint32_t* d, const uint32_t* a, uint32_t b0, uint32_t b1) {
    asm volatile("mma.sync.aligned.m16n8k16.row.col.f16.f16.f16.f16 "
                 "{%0,%1}, {%2,%3,%4,%5}, {%6,%7}, {%0,%1};\n"
                 : "+r"(d[0]), "+r"(d[1])
                 : "r"(a[0]), "r"(a[1]), "r"(a[2]), "r"(a[3]), "r"(b0), "r"(b1));
}
__device__ __forceinline__ void cp16(uint32_t dst, const void* src) {
    asm volatile("cp.async.cg.shared.global [%0], [%1], 16;\n" :: "r"(dst), "l"(src));
}
__device__ __forceinline__ void cp_commit() { asm volatile("cp.async.commit_group;\n"); }
template<int N> __device__ __forceinline__ void cp_wait() {
    asm volatile("cp.async.wait_group %0;\n" :: "n"(N));
}

// ---------------- prep ---------------------------------------------------------
__global__ __launch_bounds__(256)
void prep_all(const float* __restrict__ wd2, const float* __restrict__ wq,
              const float* __restrict__ wk, const float* __restrict__ wv,
              const float* __restrict__ wo, const float* __restrict__ bk,
              const float* __restrict__ bv,
              __half* __restrict__ Wd2, __half* __restrict__ Wq,
              __half* __restrict__ Wkv, __half* __restrict__ Wo,
              float* __restrict__ bkv)
{
    int t = blockIdx.x * 256 + threadIdx.x;
    if (t < 32768)       Wd2[t] = __float2half_rn(wd2[t]);
    else if (t < 98304)  { int i = t - 32768;  Wq[i]  = __float2half_rn(wq[i]); }
    else if (t < 163840) { int i = t - 98304;  Wkv[i] = __float2half_rn(wk[i]); }
    else if (t < 229376) { int i = t - 163840; Wkv[65536 + i] = __float2half_rn(wv[i]); }
    else if (t < 294912) { int i = t - 229376; Wo[i]  = __float2half_rn(wo[i]); }
    else if (t < 295424) { int i = t - 294912; bkv[i] = (i < 256) ? bk[i] : bv[i - 256]; }
}

// ---------------- collaborator fp32 -> fp16 (8 elems/thread) --------------------
__global__ __launch_bounds__(256)
void conv_coll(const float* __restrict__ s, __half* __restrict__ d)
{
    int t = blockIdx.x * 256 + threadIdx.x;
    float4 a = reinterpret_cast<const float4*>(s)[2 * t];
    float4 b = reinterpret_cast<const float4*>(s)[2 * t + 1];
    __half2 h0 = __floats2half2_rn(a.x, a.y), h1 = __floats2half2_rn(a.z, a.w);
    __half2 h2 = __floats2half2_rn(b.x, b.y), h3 = __floats2half2_rn(b.z, b.w);
    reinterpret_cast<uint4*>(d)[t] = make_uint4(
        *reinterpret_cast<uint32_t*>(&h0), *reinterpret_cast<uint32_t*>(&h1),
        *reinterpret_cast<uint32_t*>(&h2), *reinterpret_cast<uint32_t*>(&h3));
}

// ---------------- demand hidden ------------------------------------------------
__global__ __launch_bounds__(256)
void hid_kernel(const float* __restrict__ D, const float* __restrict__ w1,
                const float* __restrict__ b1, __half* __restrict__ Hout)
{
    int t = blockIdx.x * blockDim.x + threadIdx.x;
    int p = t & (P_PIX - 1);
    int c = t >> 15;
    float h = b1[c]
            + w1[c * 3 + 0] * D[p]
            + w1[c * 3 + 1] * D[P_PIX + p]
            + w1[c * 3 + 2] * D[2 * P_PIX + p];
    Hout[(size_t)c * P_PIX + p] = __float2half_rn(fmaxf(h, 0.f));
}

// ---------------- pipelined fp16 tensor-core GEMM (64x64 warp tiles) ------------
constexpr int ASZ   = 128 * 40;
constexpr int BSZ16 = 32 * 136;
constexpr int NS16  = 4;
constexpr int SMEM16 = NS16 * (ASZ + BSZ16) * 2;   // 75776 B -> 2 CTAs/SM

template<bool ADD2, bool OUT_HALF, bool ACC16>
__global__ __launch_bounds__(128)
void gemm_pipe(const __half* __restrict__ W, const float* __restrict__ bias,
               const __half* __restrict__ B,
               const float* __restrict__ add1, const float* __restrict__ add2,
               void* __restrict__ Cv,
               int K, int ldb, size_t bBatch, int batchN, int ldc, size_t cBatch)
{
    constexpr int NS = NS16;
    extern __shared__ __half smem[];
    __half* Asm = smem;
    __half* Bsm = smem + NS * ASZ;

    const int tid  = threadIdx.x;
    const int lane = tid & 31;
    const int warp = tid >> 5;
    const int warp_row = (warp & 1) * 64;
    const int warp_col = (warp >> 1) * 64;

    const int mtile0 = blockIdx.x * 128;
    const int ntile0 = blockIdx.y * 128;
    const int g  = ntile0 / batchN;
    const int p0 = ntile0 - g * batchN;

    const int KT = K >> 5;
    const __half* Bg = B + (size_t)g * bBatch;

    auto load_stage = [&](int kt, int s) {
        int k0 = kt << 5;
        __half* As = Asm + s * ASZ;
        __half* Bs = Bsm + s * BSZ16;
        #pragma unroll
        for (int i = 0; i < 4; i++) {
            int idx = tid + i * 128;
            int r = idx >> 2, c8 = (idx & 3) << 3;
            cp16((uint32_t)__cvta_generic_to_shared(As + r * 40 + c8),
                 W + (size_t)(mtile0 + r) * K + k0 + c8);
        }
        #pragma unroll
        for (int i = 0; i < 4; i++) {
            int idx = tid + i * 128;
            int r = idx >> 4, c8 = (idx & 15) << 3;
            cp16((uint32_t)__cvta_generic_to_shared(Bs + r * 136 + c8),
                 Bg + (size_t)(k0 + r) * ldb + p0 + c8);
        }
    };

    float    accf[ACC16 ? 1 : 4][8][4];
    uint32_t acch[ACC16 ? 4 : 1][8][2];
    #pragma unroll
    for (int i = 0; i < (ACC16 ? 1 : 4); i++)
        #pragma unroll
        for (int j = 0; j < 8; j++)
            #pragma unroll
            for (int t = 0; t < 4; t++) accf[i][j][t] = 0.f;
    #pragma unroll
    for (int i = 0; i < (ACC16 ? 4 : 1); i++)
        #pragma unroll
        for (int j = 0; j < 8; j++) { acch[i][j][0] = 0u; acch[i][j][1] = 0u; }

    #pragma unroll
    for (int s = 0; s < NS - 1; s++) {
        if (s < KT) load_stage(s, s);
        cp_commit();
    }

    for (int kt = 0; kt < KT; kt++) {
        cp_wait<NS - 2>();
        __syncthreads();

        int nk = kt + NS - 1;
        if (nk < KT) load_stage(nk, nk % NS);
        cp_commit();

        const int sc = kt % NS;
        const __half* As = Asm + sc * ASZ;
        const __half* Bs = Bsm + sc * BSZ16;

        #pragma unroll
        for (int kk = 0; kk < 32; kk += 16) {
            uint32_t a[4][4];
            #pragma unroll
            for (int mt = 0; mt < 4; mt++) {
                uint32_t addr = (uint32_t)__cvta_generic_to_shared(
                    As + (warp_row + mt * 16 + (lane & 15)) * 40 + kk + ((lane >> 4) << 3));
                ldmx4(a[mt][0], a[mt][1], a[mt][2], a[mt][3], addr);
            }
            #pragma unroll
            for (int j = 0; j < 4; j++) {
                uint32_t b0, b1, b2, b3;
                uint32_t addr = (uint32_t)__cvta_generic_to_shared(
                    Bs + (kk + (lane & 15)) * 136 + warp_col + j * 16 + ((lane >> 4) << 3));
                ldmx4t(b0, b1, b2, b3, addr);
                #pragma unroll
                for (int mt = 0; mt < 4; mt++) {
                    if (ACC16) {
                        mma16816h(acch[mt][2 * j],     a[mt], b0, b1);
                        mma16816h(acch[mt][2 * j + 1], a[mt], b2, b3);
                    } else {
                        mma16816(accf[mt][2 * j],     a[mt], b0, b1);
                        mma16816(accf[mt][2 * j + 1], a[mt], b2, b3);
                    }
                }
            }
        }
    }

    // epilogue
    __half* Ch = (__half*)Cv + (size_t)g * cBatch;
    float*  Cf = (float*)Cv  + (size_t)g * cBatch;
    #pragma unroll
    for (int mt = 0; mt < 4; mt++) {
        int r = warp_row + mt * 16 + (lane >> 2);
        #pragma unroll
        for (int rr = 0; rr < 2; rr++) {
            int gr = mtile0 + r + rr * 8;
            float bsv = bias[gr];
            #pragma unroll
            for (int j = 0; j < 8; j++) {
                int px = p0 + warp_col + j * 8 + ((lane & 3) << 1);
                float v0, v1;
                if (ACC16) {
                    __half2 hh = *reinterpret_cast<__half2*>(&acch[mt][j][rr]);
                    v0 = __half2float(__low2half(hh))  + bsv;
                    v1 = __half2float(__high2half(hh)) + bsv;
                } else {
                    v0 = accf[mt][j][rr * 2 + 0] + bsv;
                    v1 = accf[mt][j][rr * 2 + 1] + bsv;
                }
                if (ADD2) {
                    size_t off = (size_t)gr * ldc + px;
                    float2 a1 = *reinterpret_cast<const float2*>(add1 + off);
                    float2 a2 = *reinterpret_cast<const float2*>(add2 + off);
                    v0 += a1.x + a2.x;
                    v1 += a1.y + a2.y;
                }
                if (OUT_HALF) {
                    *reinterpret_cast<__half2*>(Ch + (size_t)gr * ldc + px) =
                        __floats2half2_rn(v0, v1);
                } else {
                    *reinterpret_cast<float2*>(Cf + (size_t)gr * ldc + px) =
                        make_float2(v0, v1);
                }
            }
        }
    }
}

// ---------------- per-pixel cross attention (half2, 2 px/thread, half-range) ---
__global__ __launch_bounds__(256)
void attn_kernel(const __half* __restrict__ Q, const __half* __restrict__ KV,
                 __half* __restrict__ A, int ppOff)
{
    int t = blockIdx.x * blockDim.x + threadIdx.x;
    int pp = ppOff + (t & (HPH - 1));
    int h  = t >> 13;

    const __half2* Q2 = reinterpret_cast<const __half2*>(Q + (size_t)h * 32 * P_PIX) + pp;
    float2 q[32];
    #pragma unroll
    for (int d = 0; d < 32; d++) q[d] = __half22float2(Q2[(size_t)d * HP]);

    float2 s[4];
    #pragma unroll
    for (int n = 0; n < 4; n++) {
        const __half2* K2 = reinterpret_cast<const __half2*>(
            KV + (size_t)n * 512 * P_PIX + (size_t)h * 32 * P_PIX) + pp;
        float ax = 0.f, ay = 0.f;
        #pragma unroll
        for (int d = 0; d < 32; d++) {
            float2 k = __half22float2(K2[(size_t)d * HP]);
            ax = fmaf(q[d].x, k.x, ax);
            ay = fmaf(q[d].y, k.y, ay);
        }
        s[n] = make_float2(ax * 0.17677669529663687f, ay * 0.17677669529663687f);
    }
    float mx = fmaxf(fmaxf(s[0].x, s[1].x), fmaxf(s[2].x, s[3].x));
    float my = fmaxf(fmaxf(s[0].y, s[1].y), fmaxf(s[2].y, s[3].y));
    float wx[4], wy[4], sx = 0.f, sy = 0.f;
    #pragma unroll
    for (int n = 0; n < 4; n++) {
        wx[n] = __expf(s[n].x - mx); sx += wx[n];
        wy[n] = __expf(s[n].y - my); sy += wy[n];
    }
    float ix = 1.f / sx, iy = 1.f / sy;
    #pragma unroll
    for (int n = 0; n < 4; n++) { wx[n] *= ix; wy[n] *= iy; }

    __half2* A2 = reinterpret_cast<__half2*>(A + (size_t)h * 32 * P_PIX) + pp;
    #pragma unroll
    for (int d = 0; d < 32; d++) {
        float ox = 0.f, oy = 0.f;
        #pragma unroll
        for (int n = 0; n < 4; n++) {
            float2 v = __half22float2(*(reinterpret_cast<const __half2*>(
                KV + (size_t)n * 512 * P_PIX + (size_t)(256 + h * 32 + d) * P_PIX) + pp));
            ox = fmaf(wx[n], v.x, ox);
            oy = fmaf(wy[n], v.y, oy);
        }
        A2[(size_t)d * HP] = __floats2half2_rn(ox, oy);
    }
}

// ---------------- launch ------------------------------------------------------
extern "C" void kernel_launch(void* const* d_in, const int* in_sizes, int n_in,
                              void* d_out, int out_size)
{
    const float* ego  = (const float*)d_in[0];
    const float* dem  = (const float*)d_in[1];
    const float* coll = (const float*)d_in[2];
    const float* w_d1 = (const float*)d_in[3];
    const float* b_d1 = (const float*)d_in[4];
    const float* w_d2 = (const float*)d_in[5];
    const float* b_d2 = (const float*)d_in[6];
    const float* wq   = (const float*)d_in[7];
    const float* bq   = (const float*)d_in[8];
    const float* wk   = (const float*)d_in[9];
    const float* bk   = (const float*)d_in[10];
    const float* wv   = (const float*)d_in[11];
    const float* bv   = (const float*)d_in[12];
    const float* wo   = (const float*)d_in[13];
    const float* bo   = (const float*)d_in[14];
    const float* pos  = (const float*)d_in[15];

    __half *H, *X, *Qb, *KV, *A, *C16, *Wd2, *Wq, *Wkv, *Wo;
    float *bkv;
    cudaGetSymbolAddress((void**)&H,   g_H);
    cudaGetSymbolAddress((void**)&X,   g_X);
    cudaGetSymbolAddress((void**)&Qb,  g_Q);
    cudaGetSymbolAddress((void**)&KV,  g_KV);
    cudaGetSymbolAddress((void**)&A,   g_A);
    cudaGetSymbolAddress((void**)&C16, g_C16);
    cudaGetSymbolAddress((void**)&Wd2, g_Wd2);
    cudaGetSymbolAddress((void**)&Wq,  g_Wq);
    cudaGetSymbolAddress((void**)&Wkv, g_Wkv);
    cudaGetSymbolAddress((void**)&Wo,  g_Wo);
    cudaGetSymbolAddress((void**)&bkv, g_bkv);

    static cudaStream_t s2 = nullptr, s3 = nullptr;
    static cudaEvent_t evP = nullptr, evV1 = nullptr, evV2 = nullptr,
                       evA1 = nullptr, evO1 = nullptr;
    if (!s2) {
        cudaStreamCreateWithFlags(&s2, cudaStreamNonBlocking);
        cudaStreamCreateWithFlags(&s3, cudaStreamNonBlocking);
        cudaEventCreateWithFlags(&evP,  cudaEventDisableTiming);
        cudaEventCreateWithFlags(&evV1, cudaEventDisableTiming);
        cudaEventCreateWithFlags(&evV2, cudaEventDisableTiming);
        cudaEventCreateWithFlags(&evA1, cudaEventDisableTiming);
        cudaEventCreateWithFlags(&evO1, cudaEventDisableTiming);

        cudaFuncSetAttribute(gemm_pipe<true, true, false>,
                             cudaFuncAttributeMaxDynamicSharedMemorySize, SMEM16);
        cudaFuncSetAttribute(gemm_pipe<false, true, false>,
                             cudaFuncAttributeMaxDynamicSharedMemorySize, SMEM16);
        cudaFuncSetAttribute(gemm_pipe<false, true, true>,
                             cudaFuncAttributeMaxDynamicSharedMemorySize, SMEM16);
        cudaFuncSetAttribute(gemm_pipe<false, false, false>,
                             cudaFuncAttributeMaxDynamicSharedMemorySize, SMEM16);
    }

    const int P = P_PIX;

    // ---- prep, then fork
    prep_all<<<1154, 256>>>(w_d2, wq, wk, wv, wo, bk, bv, Wd2, Wq, Wkv, Wo, bkv);
    cudaEventRecord(evP, 0);

    // ---- s2: coll->fp16 (hidden under main's hid/X/Q), K GEMM, V in pixel halves
    cudaStreamWaitEvent(s2, evP, 0);
    conv_coll<<<16384, 256, 0, s2>>>(coll, C16);
    // K = Wk @ C16 + bk (f16-acc), all pixels of all 4 collabs, grid 2048
    gemm_pipe<false, true, true><<<dim3(2, (4 * P) / 128), 128, SMEM16, s2>>>(
        Wkv, bkv, C16, nullptr, nullptr, KV,
        256, P, (size_t)256 * P, P, P, (size_t)512 * P);
    // V half 1: pixels [0, P/2) of all 4 collabs, grid 1024
    gemm_pipe<false, true, false><<<dim3(2, (4 * (P / 2)) / 128), 128, SMEM16, s2>>>(
        Wkv + 65536, bkv + 256, C16, nullptr, nullptr,
        (void*)(KV + (size_t)256 * P),
        256, P, (size_t)256 * P, P / 2, P, (size_t)512 * P);
    cudaEventRecord(evV1, s2);
    // V half 2: pixels [P/2, P)
    gemm_pipe<false, true, false><<<dim3(2, (4 * (P / 2)) / 128), 128, SMEM16, s2>>>(
        Wkv + 65536, bkv + 256, C16 + P / 2, nullptr, nullptr,
        (void*)(KV + (size_t)256 * P + P / 2),
        256, P, (size_t)256 * P, P / 2, P, (size_t)512 * P);
    cudaEventRecord(evV2, s2);

    // ---- main stream: hid -> X -> Q (tensor; overlaps conv + part of K)
    hid_kernel<<<(128 * P) / 256, 256>>>(dem, w_d1, b_d1, H);
    gemm_pipe<true, true, false><<<dim3(2, P / 128), 128, SMEM16>>>(
        Wd2, b_d2, H, ego, pos, X, 128, P, 0, P, P, 0);
    gemm_pipe<false, true, false><<<dim3(2, P / 128), 128, SMEM16>>>(
        Wq, bq, X, nullptr, nullptr, Qb, 256, P, 0, P, P, 0);

    // ---- attn half 1 (needs K + V-h1): overlaps V-h2 on complementary pipes
    cudaStreamWaitEvent(0, evV1, 0);
    attn_kernel<<<(8 * HPH) / 256, 256>>>(Qb, KV, A, 0);
    cudaEventRecord(evA1, 0);

    // ---- O(half1) on s3 as soon as A-h1 is ready
    cudaStreamWaitEvent(s3, evA1, 0);
    gemm_pipe<false, false, false><<<dim3(2, (P / 2) / 128), 128, SMEM16, s3>>>(
        Wo, bo, A, nullptr, nullptr, d_out, 256, P, 0, P, P, 0);
    cudaEventRecord(evO1, s3);

    // ---- attn half 2 after V-h2, then O(half2)
    cudaStreamWaitEvent(0, evV2, 0);
    attn_kernel<<<(8 * HPH) / 256, 256>>>(Qb, KV, A, HPH);
    gemm_pipe<false, false, false><<<dim3(2, (P / 2) / 128), 128, SMEM16>>>(
        Wo, bo, A + HP, nullptr, nullptr, (float*)d_out + HP, 256, P, 0, P, P, 0);

    cudaStreamWaitEvent(0, evO1, 0);
}

// round 15
// speedup vs baseline: 1.0877x; 1.0578x over previous
#include <cuda_runtime.h>
#include <cuda_fp16.h>
#include <cstdint>

#define P_PIX 32768            // H*W
#define HP    16384            // P/2
#define HPH   8192             // HP/2

// ---------------- scratch (static device globals) ----------------------------
__device__ __half g_H  [128u * 32768u];         //  8 MB hidden [128][P]
__device__ __half g_X  [256u * 32768u];         // 16 MB query_state fp16 [256][P]
__device__ __half g_Q  [256u * 32768u];         // 16 MB
__device__ __half g_KV [4u * 512u * 32768u];    // 128 MB per collab: K rows 0..255, V rows 256..511
__device__ __half g_A  [256u * 32768u];         // 16 MB
__device__ __half g_C16[4u * 256u * 32768u];    // 64 MB collaborator features fp16 [4][256][P]
__device__ __half g_Wd2[256 * 128];
__device__ __half g_Wq [256 * 256];
__device__ __half g_Wkv[512 * 256];             // [wk ; wv]
__device__ __half g_Wo [256 * 256];
__device__ float  g_bkv[512];

// ---------------- PTX helpers -------------------------------------------------
__device__ __forceinline__ void ldmx4(uint32_t& r0, uint32_t& r1, uint32_t& r2, uint32_t& r3, uint32_t addr) {
    asm volatile("ldmatrix.sync.aligned.m8n8.x4.shared.b16 {%0,%1,%2,%3}, [%4];\n"
                 : "=r"(r0), "=r"(r1), "=r"(r2), "=r"(r3) : "r"(addr));
}
__device__ __forceinline__ void ldmx4t(uint32_t& r0, uint32_t& r1, uint32_t& r2, uint32_t& r3, uint32_t addr) {
    asm volatile("ldmatrix.sync.aligned.m8n8.x4.trans.shared.b16 {%0,%1,%2,%3}, [%4];\n"
                 : "=r"(r0), "=r"(r1), "=r"(r2), "=r"(r3) : "r"(addr));
}
__device__ __forceinline__ void mma16816(float* d, const uint32_t* a, uint32_t b0, uint32_t b1) {
    asm volatile("mma.sync.aligned.m16n8k16.row.col.f32.f16.f16.f32 "
                 "{%0,%1,%2,%3}, {%4,%5,%6,%7}, {%8,%9}, {%0,%1,%2,%3};\n"
                 : "+f"(d[0]), "+f"(d[1]), "+f"(d[2]), "+f"(d[3])
                 : "r"(a[0]), "r"(a[1]), "r"(a[2]), "r"(a[3]), "r"(b0), "r"(b1));
}
__device__ __forceinline__ void cp16(uint32_t dst, const void* src) {
    asm volatile("cp.async.cg.shared.global [%0], [%1], 16;\n" :: "r"(dst), "l"(src));
}
__device__ __forceinline__ void cp_commit() { asm volatile("cp.async.commit_group;\n"); }
template<int N> __device__ __forceinline__ void cp_wait() {
    asm volatile("cp.async.wait_group %0;\n" :: "n"(N));
}

// ---------------- prep ---------------------------------------------------------
__global__ __launch_bounds__(256)
void prep_all(const float* __restrict__ wd2, const float* __restrict__ wq,
              const float* __restrict__ wk, const float* __restrict__ wv,
              const float* __restrict__ wo, const float* __restrict__ bk,
              const float* __restrict__ bv,
              __half* __restrict__ Wd2, __half* __restrict__ Wq,
              __half* __restrict__ Wkv, __half* __restrict__ Wo,
              float* __restrict__ bkv)
{
    int t = blockIdx.x * 256 + threadIdx.x;
    if (t < 32768)       Wd2[t] = __float2half_rn(wd2[t]);
    else if (t < 98304)  { int i = t - 32768;  Wq[i]  = __float2half_rn(wq[i]); }
    else if (t < 163840) { int i = t - 98304;  Wkv[i] = __float2half_rn(wk[i]); }
    else if (t < 229376) { int i = t - 163840; Wkv[65536 + i] = __float2half_rn(wv[i]); }
    else if (t < 294912) { int i = t - 229376; Wo[i]  = __float2half_rn(wo[i]); }
    else if (t < 295424) { int i = t - 294912; bkv[i] = (i < 256) ? bk[i] : bv[i - 256]; }
}

// ---------------- collaborator fp32 -> fp16 (8 elems/thread) --------------------
__global__ __launch_bounds__(256)
void conv_coll(const float* __restrict__ s, __half* __restrict__ d)
{
    int t = blockIdx.x * 256 + threadIdx.x;
    float4 a = reinterpret_cast<const float4*>(s)[2 * t];
    float4 b = reinterpret_cast<const float4*>(s)[2 * t + 1];
    __half2 h0 = __floats2half2_rn(a.x, a.y), h1 = __floats2half2_rn(a.z, a.w);
    __half2 h2 = __floats2half2_rn(b.x, b.y), h3 = __floats2half2_rn(b.z, b.w);
    reinterpret_cast<uint4*>(d)[t] = make_uint4(
        *reinterpret_cast<uint32_t*>(&h0), *reinterpret_cast<uint32_t*>(&h1),
        *reinterpret_cast<uint32_t*>(&h2), *reinterpret_cast<uint32_t*>(&h3));
}

// ---------------- demand hidden ------------------------------------------------
__global__ __launch_bounds__(256)
void hid_kernel(const float* __restrict__ D, const float* __restrict__ w1,
                const float* __restrict__ b1, __half* __restrict__ Hout)
{
    int t = blockIdx.x * blockDim.x + threadIdx.x;
    int p = t & (P_PIX - 1);
    int c = t >> 15;
    float h = b1[c]
            + w1[c * 3 + 0] * D[p]
            + w1[c * 3 + 1] * D[P_PIX + p]
            + w1[c * 3 + 2] * D[2 * P_PIX + p];
    Hout[(size_t)c * P_PIX + p] = __float2half_rn(fmaxf(h, 0.f));
}

// ---------------- pipelined fp16 tensor-core GEMM (64x64 warp tiles) ------------
constexpr int ASZ   = 128 * 40;
constexpr int BSZ16 = 32 * 136;
constexpr int NS16  = 4;
constexpr int SMEM16 = NS16 * (ASZ + BSZ16) * 2;   // 75776 B -> 2 CTAs/SM

template<bool ADD2, bool OUT_HALF>
__global__ __launch_bounds__(128)
void gemm_pipe(const __half* __restrict__ W, const float* __restrict__ bias,
               const __half* __restrict__ B,
               const float* __restrict__ add1, const float* __restrict__ add2,
               void* __restrict__ Cv,
               int K, int ldb, size_t bBatch, int batchN, int ldc, size_t cBatch)
{
    constexpr int NS = NS16;
    extern __shared__ __half smem[];
    __half* Asm = smem;
    __half* Bsm = smem + NS * ASZ;

    const int tid  = threadIdx.x;
    const int lane = tid & 31;
    const int warp = tid >> 5;
    const int warp_row = (warp & 1) * 64;
    const int warp_col = (warp >> 1) * 64;

    const int mtile0 = blockIdx.x * 128;
    const int ntile0 = blockIdx.y * 128;
    const int g  = ntile0 / batchN;
    const int p0 = ntile0 - g * batchN;

    const int KT = K >> 5;
    const __half* Bg = B + (size_t)g * bBatch;

    auto load_stage = [&](int kt, int s) {
        int k0 = kt << 5;
        __half* As = Asm + s * ASZ;
        __half* Bs = Bsm + s * BSZ16;
        #pragma unroll
        for (int i = 0; i < 4; i++) {
            int idx = tid + i * 128;
            int r = idx >> 2, c8 = (idx & 3) << 3;
            cp16((uint32_t)__cvta_generic_to_shared(As + r * 40 + c8),
                 W + (size_t)(mtile0 + r) * K + k0 + c8);
        }
        #pragma unroll
        for (int i = 0; i < 4; i++) {
            int idx = tid + i * 128;
            int r = idx >> 4, c8 = (idx & 15) << 3;
            cp16((uint32_t)__cvta_generic_to_shared(Bs + r * 136 + c8),
                 Bg + (size_t)(k0 + r) * ldb + p0 + c8);
        }
    };

    float acc[4][8][4];
    #pragma unroll
    for (int i = 0; i < 4; i++)
        #pragma unroll
        for (int j = 0; j < 8; j++)
            #pragma unroll
            for (int t = 0; t < 4; t++) acc[i][j][t] = 0.f;

    #pragma unroll
    for (int s = 0; s < NS - 1; s++) {
        if (s < KT) load_stage(s, s);
        cp_commit();
    }

    for (int kt = 0; kt < KT; kt++) {
        cp_wait<NS - 2>();
        __syncthreads();

        int nk = kt + NS - 1;
        if (nk < KT) load_stage(nk, nk % NS);
        cp_commit();

        const int sc = kt % NS;
        const __half* As = Asm + sc * ASZ;
        const __half* Bs = Bsm + sc * BSZ16;

        #pragma unroll
        for (int kk = 0; kk < 32; kk += 16) {
            uint32_t a[4][4];
            #pragma unroll
            for (int mt = 0; mt < 4; mt++) {
                uint32_t addr = (uint32_t)__cvta_generic_to_shared(
                    As + (warp_row + mt * 16 + (lane & 15)) * 40 + kk + ((lane >> 4) << 3));
                ldmx4(a[mt][0], a[mt][1], a[mt][2], a[mt][3], addr);
            }
            #pragma unroll
            for (int j = 0; j < 4; j++) {
                uint32_t b0, b1, b2, b3;
                uint32_t addr = (uint32_t)__cvta_generic_to_shared(
                    Bs + (kk + (lane & 15)) * 136 + warp_col + j * 16 + ((lane >> 4) << 3));
                ldmx4t(b0, b1, b2, b3, addr);
                #pragma unroll
                for (int mt = 0; mt < 4; mt++) {
                    mma16816(acc[mt][2 * j],     a[mt], b0, b1);
                    mma16816(acc[mt][2 * j + 1], a[mt], b2, b3);
                }
            }
        }
    }

    // epilogue
    __half* Ch = (__half*)Cv + (size_t)g * cBatch;
    float*  Cf = (float*)Cv  + (size_t)g * cBatch;
    #pragma unroll
    for (int mt = 0; mt < 4; mt++) {
        int r = warp_row + mt * 16 + (lane >> 2);
        #pragma unroll
        for (int rr = 0; rr < 2; rr++) {
            int gr = mtile0 + r + rr * 8;
            float bsv = bias[gr];
            #pragma unroll
            for (int j = 0; j < 8; j++) {
                int px = p0 + warp_col + j * 8 + ((lane & 3) << 1);
                float v0 = acc[mt][j][rr * 2 + 0] + bsv;
                float v1 = acc[mt][j][rr * 2 + 1] + bsv;
                if (ADD2) {
                    size_t off = (size_t)gr * ldc + px;
                    float2 a1 = *reinterpret_cast<const float2*>(add1 + off);
                    float2 a2 = *reinterpret_cast<const float2*>(add2 + off);
                    v0 += a1.x + a2.x;
                    v1 += a1.y + a2.y;
                }
                if (OUT_HALF) {
                    *reinterpret_cast<__half2*>(Ch + (size_t)gr * ldc + px) =
                        __floats2half2_rn(v0, v1);
                } else {
                    *reinterpret_cast<float2*>(Cf + (size_t)gr * ldc + px) =
                        make_float2(v0, v1);
                }
            }
        }
    }
}

// ---------------- per-pixel cross attention (half2, 2 px/thread, half-range) ---
__global__ __launch_bounds__(256)
void attn_kernel(const __half* __restrict__ Q, const __half* __restrict__ KV,
                 __half* __restrict__ A, int ppOff)
{
    int t = blockIdx.x * blockDim.x + threadIdx.x;
    int pp = ppOff + (t & (HPH - 1));
    int h  = t >> 13;

    const __half2* Q2 = reinterpret_cast<const __half2*>(Q + (size_t)h * 32 * P_PIX) + pp;
    float2 q[32];
    #pragma unroll
    for (int d = 0; d < 32; d++) q[d] = __half22float2(Q2[(size_t)d * HP]);

    float2 s[4];
    #pragma unroll
    for (int n = 0; n < 4; n++) {
        const __half2* K2 = reinterpret_cast<const __half2*>(
            KV + (size_t)n * 512 * P_PIX + (size_t)h * 32 * P_PIX) + pp;
        float ax = 0.f, ay = 0.f;
        #pragma unroll
        for (int d = 0; d < 32; d++) {
            float2 k = __half22float2(K2[(size_t)d * HP]);
            ax = fmaf(q[d].x, k.x, ax);
            ay = fmaf(q[d].y, k.y, ay);
        }
        s[n] = make_float2(ax * 0.17677669529663687f, ay * 0.17677669529663687f);
    }
    float mx = fmaxf(fmaxf(s[0].x, s[1].x), fmaxf(s[2].x, s[3].x));
    float my = fmaxf(fmaxf(s[0].y, s[1].y), fmaxf(s[2].y, s[3].y));
    float wx[4], wy[4], sx = 0.f, sy = 0.f;
    #pragma unroll
    for (int n = 0; n < 4; n++) {
        wx[n] = __expf(s[n].x - mx); sx += wx[n];
        wy[n] = __expf(s[n].y - my); sy += wy[n];
    }
    float ix = 1.f / sx, iy = 1.f / sy;
    #pragma unroll
    for (int n = 0; n < 4; n++) { wx[n] *= ix; wy[n] *= iy; }

    __half2* A2 = reinterpret_cast<__half2*>(A + (size_t)h * 32 * P_PIX) + pp;
    #pragma unroll
    for (int d = 0; d < 32; d++) {
        float ox = 0.f, oy = 0.f;
        #pragma unroll
        for (int n = 0; n < 4; n++) {
            float2 v = __half22float2(*(reinterpret_cast<const __half2*>(
                KV + (size_t)n * 512 * P_PIX + (size_t)(256 + h * 32 + d) * P_PIX) + pp));
            ox = fmaf(wx[n], v.x, ox);
            oy = fmaf(wy[n], v.y, oy);
        }
        A2[(size_t)d * HP] = __floats2half2_rn(ox, oy);
    }
}

// ---------------- launch ------------------------------------------------------
extern "C" void kernel_launch(void* const* d_in, const int* in_sizes, int n_in,
                              void* d_out, int out_size)
{
    const float* ego  = (const float*)d_in[0];
    const float* dem  = (const float*)d_in[1];
    const float* coll = (const float*)d_in[2];
    const float* w_d1 = (const float*)d_in[3];
    const float* b_d1 = (const float*)d_in[4];
    const float* w_d2 = (const float*)d_in[5];
    const float* b_d2 = (const float*)d_in[6];
    const float* wq   = (const float*)d_in[7];
    const float* bq   = (const float*)d_in[8];
    const float* wk   = (const float*)d_in[9];
    const float* bk   = (const float*)d_in[10];
    const float* wv   = (const float*)d_in[11];
    const float* bv   = (const float*)d_in[12];
    const float* wo   = (const float*)d_in[13];
    const float* bo   = (const float*)d_in[14];
    const float* pos  = (const float*)d_in[15];

    __half *H, *X, *Qb, *KV, *A, *C16, *Wd2, *Wq, *Wkv, *Wo;
    float *bkv;
    cudaGetSymbolAddress((void**)&H,   g_H);
    cudaGetSymbolAddress((void**)&X,   g_X);
    cudaGetSymbolAddress((void**)&Qb,  g_Q);
    cudaGetSymbolAddress((void**)&KV,  g_KV);
    cudaGetSymbolAddress((void**)&A,   g_A);
    cudaGetSymbolAddress((void**)&C16, g_C16);
    cudaGetSymbolAddress((void**)&Wd2, g_Wd2);
    cudaGetSymbolAddress((void**)&Wq,  g_Wq);
    cudaGetSymbolAddress((void**)&Wkv, g_Wkv);
    cudaGetSymbolAddress((void**)&Wo,  g_Wo);
    cudaGetSymbolAddress((void**)&bkv, g_bkv);

    static cudaStream_t s2 = nullptr, s3 = nullptr;
    static cudaEvent_t evP = nullptr, evKV = nullptr, evA1 = nullptr, evO1 = nullptr;
    if (!s2) {
        cudaStreamCreateWithFlags(&s2, cudaStreamNonBlocking);
        cudaStreamCreateWithFlags(&s3, cudaStreamNonBlocking);
        cudaEventCreateWithFlags(&evP,  cudaEventDisableTiming);
        cudaEventCreateWithFlags(&evKV, cudaEventDisableTiming);
        cudaEventCreateWithFlags(&evA1, cudaEventDisableTiming);
        cudaEventCreateWithFlags(&evO1, cudaEventDisableTiming);

        cudaFuncSetAttribute(gemm_pipe<true, true>,
                             cudaFuncAttributeMaxDynamicSharedMemorySize, SMEM16);
        cudaFuncSetAttribute(gemm_pipe<false, true>,
                             cudaFuncAttributeMaxDynamicSharedMemorySize, SMEM16);
        cudaFuncSetAttribute(gemm_pipe<false, false>,
                             cudaFuncAttributeMaxDynamicSharedMemorySize, SMEM16);
    }

    const int P = P_PIX;

    // ---- s2: coll conversion immediately (depends only on coll, not prep)
    conv_coll<<<16384, 256, 0, s2>>>(coll, C16);

    // ---- main: prep (weights/biases)
    prep_all<<<1154, 256>>>(w_d2, wq, wk, wv, wo, bk, bv, Wd2, Wq, Wkv, Wo, bkv);
    cudaEventRecord(evP, 0);

    // ---- s2: single stacked [K;V] GEMM (M=512, grid 4x1024 = 4096 CTAs)
    cudaStreamWaitEvent(s2, evP, 0);
    gemm_pipe<false, true><<<dim3(4, (4 * P) / 128), 128, SMEM16, s2>>>(
        Wkv, bkv, C16, nullptr, nullptr, KV,
        256, P, (size_t)256 * P, P, P, (size_t)512 * P);
    cudaEventRecord(evKV, s2);

    // ---- main stream: hid -> X -> Q (tensor; overlaps conv + part of KV)
    hid_kernel<<<(128 * P) / 256, 256>>>(dem, w_d1, b_d1, H);
    gemm_pipe<true, true><<<dim3(2, P / 128), 128, SMEM16>>>(
        Wd2, b_d2, H, ego, pos, X, 128, P, 0, P, P, 0);
    gemm_pipe<false, true><<<dim3(2, P / 128), 128, SMEM16>>>(
        Wq, bq, X, nullptr, nullptr, Qb, 256, P, 0, P, P, 0);

    // ---- join: attention half 1
    cudaStreamWaitEvent(0, evKV, 0);
    attn_kernel<<<(8 * HPH) / 256, 256>>>(Qb, KV, A, 0);
    cudaEventRecord(evA1, 0);

    // ---- O(half1) on s3 concurrently with attn(half2)
    cudaStreamWaitEvent(s3, evA1, 0);
    gemm_pipe<false, false><<<dim3(2, (P / 2) / 128), 128, SMEM16, s3>>>(
        Wo, bo, A, nullptr, nullptr, d_out, 256, P, 0, P, P, 0);
    cudaEventRecord(evO1, s3);

    attn_kernel<<<(8 * HPH) / 256, 256>>>(Qb, KV, A, HPH);

    // ---- O(half2)
    gemm_pipe<false, false><<<dim3(2, (P / 2) / 128), 128, SMEM16>>>(
        Wo, bo, A + HP, nullptr, nullptr, (float*)d_out + HP, 256, P, 0, P, P, 0);

    cudaStreamWaitEvent(0, evO1, 0);
}